// round 2
// baseline (speedup 1.0000x reference)
#include <cuda_runtime.h>
#include <math.h>

// Problem constants
#define S   2048
#define B   4
#define D   1024
#define H   16
#define M_ROWS (S*B)   // 8192 rows, time-major: row = t*B + b

// ---------------------------------------------------------------------------
// Scratch buffers (device globals; no allocation allowed)
// ---------------------------------------------------------------------------
__device__ float g_ret   [(size_t)M_ROWS*D];   // retained = q * r
__device__ float g_inp   [(size_t)M_ROWS*D];   // inp = retained@Wi^T + bi
__device__ float g_gpre  [(size_t)M_ROWS*D];   // inp@Wg^T + bg
__device__ float g_c     [(size_t)M_ROWS*D];   // c = inp@Bm^T; later d = u@A^T + c
__device__ float g_gate  [(size_t)M_ROWS*D];   // sigmoid(gpre)
__device__ float g_u     [(size_t)M_ROWS*D];   // (1-gate)*inp
__device__ float g_states[(size_t)M_ROWS*D];   // state_t sequence
__device__ unsigned int g_bar;

__global__ void init_bar_kernel() { g_bar = 0u; }

// ---------------------------------------------------------------------------
// Phase 1: retention scan with decay halo.
// r[t] = decay*r[t-1] + k_t*v_t ; retained[t] = q_t*r[t]
// decay = 0.9 -> contributions older than 256 steps are < 2e-12 relative, so
// each 128-step chunk rescans a 256-step halo and is fully parallel.
// ---------------------------------------------------------------------------
__global__ void scan_kernel(const float* __restrict__ q,
                            const float* __restrict__ k,
                            const float* __restrict__ v,
                            const float* __restrict__ dec)
{
    int chunk = blockIdx.x;                 // 16 chunks of 128 steps
    int b     = blockIdx.y;                 // batch
    int d     = blockIdx.z*256 + threadIdx.x;
    float decay = dec[d >> 6];              // per-head (hd = 64)
    int t0 = chunk*128;
    int start = t0 - 256; if (start < 0) start = 0;
    float r = 0.f;
    const float* kb = k + ((size_t)b*S)*D + d;
    const float* vb = v + ((size_t)b*S)*D + d;
    const float* qb = q + ((size_t)b*S)*D + d;
    for (int tt = start; tt < t0 + 128; ++tt) {
        size_t off = (size_t)tt*D;
        r = decay*r + kb[off]*vb[off];
        if (tt >= t0) {
            g_ret[((size_t)tt*B + b)*D + d] = qb[off]*r;
        }
    }
}

// ---------------------------------------------------------------------------
// fp32 SGEMM:  C[m,n] = sum_k X[m,k]*W[n,k] (+bias[n]) (+Cin[m,n])
// M=8192, N=K=1024 fixed. 128x128 tile, BK=8, 256 threads, 8x8 per thread.
// permute=1: store row m=(t*B+b) at output row (b*S+t)  (for final output).
// ---------------------------------------------------------------------------
__global__ __launch_bounds__(256, 2)
void sgemm_kernel(const float* __restrict__ X, const float* __restrict__ W,
                  const float* __restrict__ bias, const float* Cin,
                  float* Cout, int permute)
{
    const int K = D, N = D;
    __shared__ float As[8][128];
    __shared__ float Bs[8][128];

    int tid = threadIdx.x;
    int m0 = blockIdx.y*128, n0 = blockIdx.x*128;
    int lrow = tid >> 1;
    int lk4  = (tid & 1)*4;
    const float4* Xg = (const float4*)(X + (size_t)(m0+lrow)*K + lk4);
    const float4* Wg = (const float4*)(W + (size_t)(n0+lrow)*K + lk4);

    int ty = tid >> 4, tx = tid & 15;

    float acc[8][8];
    #pragma unroll
    for (int i = 0; i < 8; ++i)
        #pragma unroll
        for (int j = 0; j < 8; ++j) acc[i][j] = 0.f;

    for (int kt = 0; kt < K/8; ++kt) {
        float4 av = Xg[kt*2];
        float4 bv = Wg[kt*2];
        __syncthreads();
        As[lk4+0][lrow] = av.x; As[lk4+1][lrow] = av.y;
        As[lk4+2][lrow] = av.z; As[lk4+3][lrow] = av.w;
        Bs[lk4+0][lrow] = bv.x; Bs[lk4+1][lrow] = bv.y;
        Bs[lk4+2][lrow] = bv.z; Bs[lk4+3][lrow] = bv.w;
        __syncthreads();
        #pragma unroll
        for (int kk = 0; kk < 8; ++kk) {
            float a_frag[8], b_frag[8];
            *(float4*)&a_frag[0] = *(const float4*)&As[kk][ty*8];
            *(float4*)&a_frag[4] = *(const float4*)&As[kk][ty*8+4];
            *(float4*)&b_frag[0] = *(const float4*)&Bs[kk][tx*8];
            *(float4*)&b_frag[4] = *(const float4*)&Bs[kk][tx*8+4];
            #pragma unroll
            for (int i = 0; i < 8; ++i)
                #pragma unroll
                for (int j = 0; j < 8; ++j)
                    acc[i][j] += a_frag[i]*b_frag[j];
        }
    }

    #pragma unroll
    for (int i = 0; i < 8; ++i) {
        int m = m0 + ty*8 + i;
        size_t obase;
        if (!permute) obase = (size_t)m*N;
        else { int t = m >> 2; int bb = m & 3; obase = ((size_t)bb*S + t)*N; }
        #pragma unroll
        for (int j = 0; j < 8; ++j) {
            int n = n0 + tx*8 + j;
            float val = acc[i][j];
            if (bias) val += bias[n];
            if (Cin)  val += Cin[(size_t)m*N + n];
            Cout[obase + n] = val;
        }
    }
}

// ---------------------------------------------------------------------------
// Phase: gate = sigmoid(gpre); u = (1-gate)*inp
// ---------------------------------------------------------------------------
__global__ void gate_kernel()
{
    size_t i = (size_t)blockIdx.x*blockDim.x + threadIdx.x;
    if (i < (size_t)M_ROWS*D) {
        float gp = g_gpre[i];
        float gt = 1.f/(1.f + expf(-gp));
        g_gate[i] = gt;
        g_u[i]    = (1.f - gt)*g_inp[i];
    }
}

// ---------------------------------------------------------------------------
// Sequential phase: state_t = tanh((g_t (*) state_{t-1}) @ A^T + d_t)
// Persistent kernel: 128 CTAs x 256 threads, 8 output cols per CTA.
// A slice lives in registers for the whole 2048-step loop.
// Grid barrier: release atomic + acquire spin on a counter.
// ---------------------------------------------------------------------------
__device__ __forceinline__ void bar_arrive(unsigned int* p) {
    unsigned int old;
    asm volatile("atom.add.release.gpu.u32 %0, [%1], 1;"
                 : "=r"(old) : "l"(p) : "memory");
}
__device__ __forceinline__ unsigned int bar_peek(unsigned int* p) {
    unsigned int v;
    asm volatile("ld.acquire.gpu.u32 %0, [%1];"
                 : "=r"(v) : "l"(p) : "memory");
    return v;
}

__global__ __launch_bounds__(256, 1)
void seq_kernel(const float* __restrict__ A)
{
    __shared__ float bl[B*D];      // blended = g (*) state_prev, 16KB
    __shared__ float red[8*16];    // warp partial sums

    int tid = threadIdx.x;
    int cg  = tid >> 7;            // col group 0..1 (4 cols each)
    int ks  = tid & 127;           // k-slice 0..127 (8 k's each)
    int k0  = ks*8;
    int colbase = blockIdx.x*8 + cg*4;

    // Register-resident A slice: 4 cols x 8 k's
    float Areg[4][8];
    #pragma unroll
    for (int c = 0; c < 4; ++c) {
        *(float4*)&Areg[c][0] = *(const float4*)(A + (size_t)(colbase+c)*D + k0);
        *(float4*)&Areg[c][4] = *(const float4*)(A + (size_t)(colbase+c)*D + k0 + 4);
    }
    unsigned int nct = gridDim.x;

    for (int t = 0; t < S; ++t) {
        // build blended into smem
        if (t == 0) {
            #pragma unroll
            for (int j = 0; j < 16; ++j) bl[j*256 + tid] = 0.f;
        } else {
            const float* grow = g_gate   + (size_t)t    *B*D;
            const float* srow = g_states + (size_t)(t-1)*B*D;
            #pragma unroll
            for (int j = 0; j < 16; ++j) {
                int e = j*256 + tid;
                bl[e] = grow[e]*srow[e];
            }
        }
        __syncthreads();

        // partial dot products: 4 batches x 4 cols over this thread's 8 k's
        float p[4][4];
        #pragma unroll
        for (int bb = 0; bb < 4; ++bb)
            #pragma unroll
            for (int c = 0; c < 4; ++c) p[bb][c] = 0.f;

        #pragma unroll
        for (int bb = 0; bb < B; ++bb) {
            float blv[8];
            *(float4*)&blv[0] = *(const float4*)&bl[bb*D + k0];
            *(float4*)&blv[4] = *(const float4*)&bl[bb*D + k0 + 4];
            #pragma unroll
            for (int c = 0; c < 4; ++c)
                #pragma unroll
                for (int kk = 0; kk < 8; ++kk)
                    p[bb][c] += blv[kk]*Areg[c][kk];
        }

        // reduce across 32 lanes (k-slices) of each warp
        #pragma unroll
        for (int off = 16; off >= 1; off >>= 1)
            #pragma unroll
            for (int bb = 0; bb < 4; ++bb)
                #pragma unroll
                for (int c = 0; c < 4; ++c)
                    p[bb][c] += __shfl_xor_sync(0xffffffffu, p[bb][c], off);

        if ((tid & 31) == 0) {
            int w = tid >> 5;
            #pragma unroll
            for (int bb = 0; bb < 4; ++bb)
                #pragma unroll
                for (int c = 0; c < 4; ++c)
                    red[w*16 + bb*4 + c] = p[bb][c];
        }
        __syncthreads();

        // final reduce over 4 warps per col group, + d_t, tanh, store state
        if (tid < 32) {
            int bb  = tid >> 3;
            int c   = tid & 7;
            int cg2 = c >> 2, c4 = c & 3;
            float sum = 0.f;
            #pragma unroll
            for (int w = 0; w < 4; ++w)
                sum += red[(cg2*4 + w)*16 + bb*4 + c4];
            int col = blockIdx.x*8 + c;
            size_t idx = ((size_t)t*B + bb)*D + col;
            float pre = sum + g_c[idx];   // g_c holds d = u@A^T + c
            g_states[idx] = tanhf(pre);
            __threadfence();
        }
        __syncthreads();

        // grid barrier
        if (tid == 0) {
            bar_arrive(&g_bar);
            unsigned int target = (unsigned int)(t + 1)*nct;
            while (bar_peek(&g_bar) < target) { }
        }
        __syncthreads();
    }
}

// ---------------------------------------------------------------------------
// Launch
// ---------------------------------------------------------------------------
extern "C" void kernel_launch(void* const* d_in, const int* in_sizes, int n_in,
                              void* d_out, int out_size)
{
    const float* q   = (const float*)d_in[0];
    const float* k   = (const float*)d_in[1];
    const float* v   = (const float*)d_in[2];
    const float* Wi  = (const float*)d_in[3];
    const float* bi  = (const float*)d_in[4];
    const float* Wg  = (const float*)d_in[5];
    const float* bg  = (const float*)d_in[6];
    const float* A   = (const float*)d_in[7];
    const float* Bm  = (const float*)d_in[8];
    const float* Wo  = (const float*)d_in[9];
    const float* bo  = (const float*)d_in[10];
    const float* dec = (const float*)d_in[11];
    float* out = (float*)d_out;

    float *ret_p, *inp_p, *gpre_p, *c_p, *u_p, *states_p;
    cudaGetSymbolAddress((void**)&ret_p,    g_ret);
    cudaGetSymbolAddress((void**)&inp_p,    g_inp);
    cudaGetSymbolAddress((void**)&gpre_p,   g_gpre);
    cudaGetSymbolAddress((void**)&c_p,      g_c);
    cudaGetSymbolAddress((void**)&u_p,      g_u);
    cudaGetSymbolAddress((void**)&states_p, g_states);

    init_bar_kernel<<<1, 1>>>();

    dim3 sg(16, 4, 4);
    scan_kernel<<<sg, 256>>>(q, k, v, dec);

    dim3 gg(D/128, M_ROWS/128);   // (8, 64)
    // inp = retained @ Wi^T + bi
    sgemm_kernel<<<gg, 256>>>(ret_p, Wi, bi, nullptr, inp_p, 0);
    // gpre = inp @ Wg^T + bg
    sgemm_kernel<<<gg, 256>>>(inp_p, Wg, bg, nullptr, gpre_p, 0);
    // c = inp @ Bm^T
    sgemm_kernel<<<gg, 256>>>(inp_p, Bm, nullptr, nullptr, c_p, 0);
    // gate, u
    gate_kernel<<<(M_ROWS*(D/256))/1, 256>>>();
    // d = u @ A^T + c   (accumulate in place into c buffer)
    sgemm_kernel<<<gg, 256>>>(u_p, A, nullptr, c_p, c_p, 0);
    // sequential state scan
    seq_kernel<<<128, 256>>>(A);
    // out = states @ Wo^T + bo, stored as [B, S, D]
    sgemm_kernel<<<gg, 256>>>(states_p, Wo, bo, nullptr, out, 1);
}

// round 4
// speedup vs baseline: 1.1680x; 1.1680x over previous
#include <cuda_runtime.h>
#include <math.h>

// Problem constants
#define S   2048
#define B   4
#define D   1024
#define M_ROWS (S*B)   // 8192 rows, time-major: row = t*B + b

typedef unsigned long long ull;

// ---------------------------------------------------------------------------
// Scratch buffers (device globals; no allocation allowed)
// ---------------------------------------------------------------------------
__device__ float g_ret   [(size_t)M_ROWS*D];
__device__ float g_inp   [(size_t)M_ROWS*D];
__device__ float g_gpre  [(size_t)M_ROWS*D];
__device__ float g_c     [(size_t)M_ROWS*D];   // c; later d = u@A^T + c
__device__ float g_gate  [(size_t)M_ROWS*D];
__device__ float g_u     [(size_t)M_ROWS*D];
__device__ float g_states[(size_t)M_ROWS*D];
__device__ unsigned int g_bar;

__global__ void init_bar_kernel() { g_bar = 0u; }

// ---------------------------------------------------------------------------
// f32x2 helpers (Blackwell packed fp32 pipe, PTX-only)
// ---------------------------------------------------------------------------
__device__ __forceinline__ ull pack2(float x, float y) {
    ull r; asm("mov.b64 %0, {%1, %2};" : "=l"(r) : "f"(x), "f"(y)); return r;
}
__device__ __forceinline__ void fma2(ull& d, ull a, ull b) {
    asm("fma.rn.f32x2 %0, %1, %2, %0;" : "+l"(d) : "l"(a), "l"(b));
}
__device__ __forceinline__ float2 unpack2(ull a) {
    float2 r; asm("mov.b64 {%0, %1}, %2;" : "=f"(r.x), "=f"(r.y) : "l"(a)); return r;
}
__device__ __forceinline__ unsigned int ld_acq(const unsigned int* p) {
    unsigned int v;
    asm volatile("ld.acquire.gpu.u32 %0, [%1];" : "=r"(v) : "l"(p) : "memory");
    return v;
}

// ---------------------------------------------------------------------------
// Phase 1: retention scan with decay halo (decay=0.9 -> 256-step halo exact
// to ~2e-12 relative).
// ---------------------------------------------------------------------------
__global__ void scan_kernel(const float* __restrict__ q,
                            const float* __restrict__ k,
                            const float* __restrict__ v,
                            const float* __restrict__ dec)
{
    int chunk = blockIdx.x;                 // 16 chunks of 128 steps
    int b     = blockIdx.y;
    int d     = blockIdx.z*256 + threadIdx.x;
    float decay = dec[d >> 6];
    int t0 = chunk*128;
    int start = t0 - 256; if (start < 0) start = 0;
    float r = 0.f;
    const float* kb = k + ((size_t)b*S)*D + d;
    const float* vb = v + ((size_t)b*S)*D + d;
    const float* qb = q + ((size_t)b*S)*D + d;
    for (int tt = start; tt < t0 + 128; ++tt) {
        size_t off = (size_t)tt*D;
        r = decay*r + kb[off]*vb[off];
        if (tt >= t0) g_ret[((size_t)tt*B + b)*D + d] = qb[off]*r;
    }
}

// ---------------------------------------------------------------------------
// fp32 SGEMM: C[m,n] = sum_k X[m,k]*W[n,k] (+bias) (+Cin). M=8192, N=K=1024.
// 128x128 tile, BK=8, 256 thr, 8x8/thread, double-buffered smem, f32x2 FMA.
// ---------------------------------------------------------------------------
__global__ __launch_bounds__(256)
void sgemm_kernel(const float* __restrict__ X, const float* __restrict__ W,
                  const float* __restrict__ bias, const float* Cin,
                  float* Cout, int permute)
{
    __shared__ float As[2][8][128];
    __shared__ float Bs[2][8][128];

    int tid = threadIdx.x;
    int m0 = blockIdx.y*128, n0 = blockIdx.x*128;
    int lrow = tid >> 1;
    int lk4  = (tid & 1)*4;
    const float4* Xg = (const float4*)(X + (size_t)(m0+lrow)*D + lk4);
    const float4* Wg = (const float4*)(W + (size_t)(n0+lrow)*D + lk4);
    int ty = tid >> 4, tx = tid & 15;

    ull acc[8][4];   // 8 rows x 4 col-pairs (f32x2 over adjacent n)
    #pragma unroll
    for (int i = 0; i < 8; ++i)
        #pragma unroll
        for (int j = 0; j < 4; ++j) acc[i][j] = 0ull;

    // prologue: fill buffer 0
    float4 ra = Xg[0], rb = Wg[0];
    As[0][lk4+0][lrow] = ra.x; As[0][lk4+1][lrow] = ra.y;
    As[0][lk4+2][lrow] = ra.z; As[0][lk4+3][lrow] = ra.w;
    Bs[0][lk4+0][lrow] = rb.x; Bs[0][lk4+1][lrow] = rb.y;
    Bs[0][lk4+2][lrow] = rb.z; Bs[0][lk4+3][lrow] = rb.w;
    __syncthreads();

    int cur = 0;
    #pragma unroll 1
    for (int kt = 0; kt < 128; ++kt) {
        float4 ra2, rb2;
        if (kt < 127) { ra2 = Xg[(kt+1)*2]; rb2 = Wg[(kt+1)*2]; }

        #pragma unroll
        for (int kk = 0; kk < 8; ++kk) {
            float4 a0 = *(const float4*)&As[cur][kk][ty*8];
            float4 a1 = *(const float4*)&As[cur][kk][ty*8+4];
            ulonglong2 b0 = *(const ulonglong2*)&Bs[cur][kk][tx*8];
            ulonglong2 b1 = *(const ulonglong2*)&Bs[cur][kk][tx*8+4];
            ull bp[4] = { b0.x, b0.y, b1.x, b1.y };
            ull ad[8];
            ad[0] = pack2(a0.x, a0.x); ad[1] = pack2(a0.y, a0.y);
            ad[2] = pack2(a0.z, a0.z); ad[3] = pack2(a0.w, a0.w);
            ad[4] = pack2(a1.x, a1.x); ad[5] = pack2(a1.y, a1.y);
            ad[6] = pack2(a1.z, a1.z); ad[7] = pack2(a1.w, a1.w);
            #pragma unroll
            for (int i = 0; i < 8; ++i)
                #pragma unroll
                for (int j = 0; j < 4; ++j)
                    fma2(acc[i][j], bp[j], ad[i]);
        }

        if (kt < 127) {
            int nb = cur ^ 1;
            As[nb][lk4+0][lrow] = ra2.x; As[nb][lk4+1][lrow] = ra2.y;
            As[nb][lk4+2][lrow] = ra2.z; As[nb][lk4+3][lrow] = ra2.w;
            Bs[nb][lk4+0][lrow] = rb2.x; Bs[nb][lk4+1][lrow] = rb2.y;
            Bs[nb][lk4+2][lrow] = rb2.z; Bs[nb][lk4+3][lrow] = rb2.w;
            __syncthreads();
            cur = nb;
        }
    }

    #pragma unroll
    for (int i = 0; i < 8; ++i) {
        int m = m0 + ty*8 + i;
        size_t obase;
        if (!permute) obase = (size_t)m*D;
        else { int t = m >> 2; int bb = m & 3; obase = ((size_t)bb*S + t)*D; }
        #pragma unroll
        for (int j = 0; j < 4; ++j) {
            float2 v = unpack2(acc[i][j]);
            int n = n0 + tx*8 + j*2;
            float v0 = v.x, v1 = v.y;
            if (bias) { v0 += bias[n]; v1 += bias[n+1]; }
            if (Cin)  { v0 += Cin[(size_t)m*D + n]; v1 += Cin[(size_t)m*D + n+1]; }
            Cout[obase + n]   = v0;
            Cout[obase + n+1] = v1;
        }
    }
}

// ---------------------------------------------------------------------------
// gate = sigmoid(gpre); u = (1-gate)*inp
// ---------------------------------------------------------------------------
__global__ void gate_kernel()
{
    size_t i = (size_t)blockIdx.x*blockDim.x + threadIdx.x;
    if (i < (size_t)M_ROWS*D) {
        float gp = g_gpre[i];
        float gt = 1.f/(1.f + expf(-gp));
        g_gate[i] = gt;
        g_u[i]    = (1.f - gt)*g_inp[i];
    }
}

// ---------------------------------------------------------------------------
// Sequential phase: state_t = tanh((g_t (*) state_{t-1}) @ A^T + d_t)
// 128 persistent CTAs x 256 thr. Thread = (cg: 4 cols) x (kslice: 8 k).
// A slice register-resident as f32x2. Blended in swizzled smem.
// Multi-value butterfly reduction: 16 values x 32 lanes in 16 SHFLs.
// ---------------------------------------------------------------------------
__device__ __forceinline__ int swz(int byteoff) {
    return byteoff ^ ((byteoff >> 3) & 0x70);
}

__global__ __launch_bounds__(256, 1)
void seq_kernel(const float* __restrict__ A)
{
    __shared__ float4 bl4[1024];     // blended [b][k], swizzled, 16KB
    __shared__ float  red[8*16];     // per-warp partials

    int tid  = threadIdx.x;
    int w    = tid >> 5, lane = tid & 31;
    int cg   = tid >> 7;             // 0..1 -> which 4 columns
    int ks   = tid & 127;            // k-slice (8 k each)
    int k0   = ks*8;
    int colbase = blockIdx.x*8 + cg*4;

    // A slice: 4 cols x 4 k-pairs, packed f32x2 (adjacent k)
    ull A2[4][4];
    #pragma unroll
    for (int c = 0; c < 4; ++c) {
        const float* ap = A + (size_t)(colbase+c)*D + k0;
        ulonglong2 u0 = *(const ulonglong2*)ap;
        ulonglong2 u1 = *(const ulonglong2*)(ap+4);
        A2[c][0] = u0.x; A2[c][1] = u0.y; A2[c][2] = u1.x; A2[c][3] = u1.y;
    }

    const float4* gate4 = (const float4*)g_gate;
    const float4* st4   = (const float4*)g_states;

    // output assignment for reducer threads (tid < 32)
    int ob = tid & 3, oc = (tid >> 2) & 3, ocg = tid >> 4;
    int ocol = blockIdx.x*8 + ocg*4 + oc;
    float dval = 0.f;
    if (tid < 32) dval = __ldg(&g_c[(size_t)ob*D + ocol]);   // d row t=0

    float4 gp[4];
    unsigned int nct = gridDim.x;

    for (int t = 0; t < S; ++t) {
        // ---- build blended into swizzled smem ----
        if (t == 0) {
            #pragma unroll
            for (int i = 0; i < 4; ++i) {
                int idx = tid + 256*i;
                bl4[swz(idx*16) >> 4] = make_float4(0.f, 0.f, 0.f, 0.f);
            }
        } else {
            #pragma unroll
            for (int i = 0; i < 4; ++i) {
                int idx = tid + 256*i;
                float4 s = st4[(size_t)(t-1)*1024 + idx];
                float4 g = gp[i];
                bl4[swz(idx*16) >> 4] =
                    make_float4(g.x*s.x, g.y*s.y, g.z*s.z, g.w*s.w);
            }
        }
        __syncthreads();

        // ---- compute: acc[c][b] over this thread's 8 k (4 f32x2 pairs) ----
        ull acc[4][4];
        #pragma unroll
        for (int c = 0; c < 4; ++c)
            #pragma unroll
            for (int b = 0; b < 4; ++b) acc[c][b] = 0ull;

        #pragma unroll
        for (int b = 0; b < 4; ++b) {
            int boff = b*4096 + k0*4;
            ulonglong2 x0 = *(const ulonglong2*)((const char*)bl4 + swz(boff));
            ulonglong2 x1 = *(const ulonglong2*)((const char*)bl4 + swz(boff+16));
            #pragma unroll
            for (int c = 0; c < 4; ++c) {
                fma2(acc[c][b], x0.x, A2[c][0]);
                fma2(acc[c][b], x0.y, A2[c][1]);
                fma2(acc[c][b], x1.x, A2[c][2]);
                fma2(acc[c][b], x1.y, A2[c][3]);
            }
        }

        // ---- horizontal add -> 16 scalars (idx = c*4 + b) ----
        float s[16];
        #pragma unroll
        for (int c = 0; c < 4; ++c)
            #pragma unroll
            for (int b = 0; b < 4; ++b) {
                float2 f = unpack2(acc[c][b]);
                s[c*4+b] = f.x + f.y;
            }

        // ---- multi-value butterfly: 16 values x 32 lanes in 16 SHFLs ----
        // After stages off=16,8,4,2 each thread holds one value,
        // index = (lane>>1)&15 (bit4->8, bit3->4, bit2->2, bit1->1),
        // summed over the 16 lanes sharing its bit0. Final off=1 completes.
        #pragma unroll
        for (int stage = 0; stage < 4; ++stage) {
            int off = 16 >> stage;
            int nv  = 8  >> stage;
            bool hi = (lane & off) != 0;
            #pragma unroll
            for (int vv = 0; vv < nv; ++vv) {
                float mine  = hi ? s[nv+vv] : s[vv];
                float other = hi ? s[vv]    : s[nv+vv];
                s[vv] = mine + __shfl_xor_sync(0xffffffffu, other, off);
            }
        }
        s[0] += __shfl_xor_sync(0xffffffffu, s[0], 1);
        if ((lane & 1) == 0)
            red[w*16 + (lane >> 1)] = s[0];

        // ---- prefetch gate row t+1 (independent of states) ----
        if (t+1 < S) {
            #pragma unroll
            for (int i = 0; i < 4; ++i)
                gp[i] = __ldg(&gate4[(size_t)(t+1)*1024 + tid + 256*i]);
        }
        __syncthreads();

        // ---- finalize: combine 4 warps, +d, tanh, store state ----
        if (tid < 32) {
            int wb = ocg*4;
            int e  = oc*4 + ob;
            float sum = red[(wb+0)*16 + e] + red[(wb+1)*16 + e]
                      + red[(wb+2)*16 + e] + red[(wb+3)*16 + e];
            float st = tanhf(sum + dval);
            g_states[((size_t)t*B + ob)*D + ocol] = st;
            if (t+1 < S)
                dval = __ldg(&g_c[((size_t)(t+1)*B + ob)*D + ocol]);
        }
        __syncthreads();

        // ---- grid barrier (skip after last step) ----
        if (t+1 < S) {
            if (tid == 0) {
                __threadfence();
                atomicAdd(&g_bar, 1u);
                unsigned int target = (unsigned int)(t + 1)*nct;
                while (ld_acq(&g_bar) < target) { }
            }
            __syncthreads();
        }
    }
}

// ---------------------------------------------------------------------------
// Launch
// ---------------------------------------------------------------------------
extern "C" void kernel_launch(void* const* d_in, const int* in_sizes, int n_in,
                              void* d_out, int out_size)
{
    const float* q   = (const float*)d_in[0];
    const float* k   = (const float*)d_in[1];
    const float* v   = (const float*)d_in[2];
    const float* Wi  = (const float*)d_in[3];
    const float* bi  = (const float*)d_in[4];
    const float* Wg  = (const float*)d_in[5];
    const float* bg  = (const float*)d_in[6];
    const float* A   = (const float*)d_in[7];
    const float* Bm  = (const float*)d_in[8];
    const float* Wo  = (const float*)d_in[9];
    const float* bo  = (const float*)d_in[10];
    const float* dec = (const float*)d_in[11];
    float* out = (float*)d_out;

    float *ret_p, *inp_p, *gpre_p, *c_p, *u_p, *states_p;
    cudaGetSymbolAddress((void**)&ret_p,    g_ret);
    cudaGetSymbolAddress((void**)&inp_p,    g_inp);
    cudaGetSymbolAddress((void**)&gpre_p,   g_gpre);
    cudaGetSymbolAddress((void**)&c_p,      g_c);
    cudaGetSymbolAddress((void**)&u_p,      g_u);
    cudaGetSymbolAddress((void**)&states_p, g_states);

    init_bar_kernel<<<1, 1>>>();

    dim3 sg(16, 4, 4);
    scan_kernel<<<sg, 256>>>(q, k, v, dec);

    dim3 gg(D/128, M_ROWS/128);   // (8, 64)
    sgemm_kernel<<<gg, 256>>>(ret_p, Wi, bi, nullptr, inp_p, 0);
    sgemm_kernel<<<gg, 256>>>(inp_p, Wg, bg, nullptr, gpre_p, 0);
    sgemm_kernel<<<gg, 256>>>(inp_p, Bm, nullptr, nullptr, c_p, 0);
    gate_kernel<<<M_ROWS*(D/256), 256>>>();
    sgemm_kernel<<<gg, 256>>>(u_p, A, nullptr, c_p, c_p, 0);
    seq_kernel<<<128, 256>>>(A);
    sgemm_kernel<<<gg, 256>>>(states_p, Wo, bo, nullptr, out, 1);
}

// round 6
// speedup vs baseline: 1.2971x; 1.1106x over previous
#include <cuda_runtime.h>
#include <math.h>

// Problem constants
#define S   2048
#define B   4
#define D   1024
#define M_ROWS (S*B)   // 8192 rows, time-major: row = t*B + b

typedef unsigned long long ull;

// ---------------------------------------------------------------------------
// Scratch buffers (device globals; no allocation allowed)
// ---------------------------------------------------------------------------
__device__ float g_ret   [(size_t)M_ROWS*D];
__device__ float g_inp   [(size_t)M_ROWS*D];
__device__ float g_gpre  [(size_t)M_ROWS*D];
__device__ float g_c     [(size_t)M_ROWS*D];   // c; later d = u@A^T + c
__device__ float g_gate  [(size_t)M_ROWS*D];
__device__ float g_u     [(size_t)M_ROWS*D];
__device__ float g_states[(size_t)M_ROWS*D];
__device__ float g_blend [2][B][D];            // double-buffered blended rows
__device__ unsigned int g_bars[128];           // 4 counters, 128B apart

__global__ void init_misc_kernel() {
    int i = blockIdx.x*blockDim.x + threadIdx.x;
    if (i < 128) g_bars[i] = 0u;
    if (i < 2*B*D) ((float*)g_blend)[i] = 0.f;
}

// ---------------------------------------------------------------------------
// f32x2 helpers (Blackwell packed fp32 pipe, PTX-only)
// ---------------------------------------------------------------------------
__device__ __forceinline__ ull pack2(float x, float y) {
    ull r; asm("mov.b64 %0, {%1, %2};" : "=l"(r) : "f"(x), "f"(y)); return r;
}
__device__ __forceinline__ void fma2(ull& d, ull a, ull b) {
    asm("fma.rn.f32x2 %0, %1, %2, %0;" : "+l"(d) : "l"(a), "l"(b));
}
__device__ __forceinline__ float2 unpack2(ull a) {
    float2 r; asm("mov.b64 {%0, %1}, %2;" : "=f"(r.x), "=f"(r.y) : "l"(a)); return r;
}
__device__ __forceinline__ unsigned int ld_acq(const unsigned int* p) {
    unsigned int v;
    asm volatile("ld.acquire.gpu.u32 %0, [%1];" : "=r"(v) : "l"(p) : "memory");
    return v;
}
__device__ __forceinline__ void ld_cg_v2u64(ull& x0, ull& x1, const float* p) {
    asm volatile("ld.global.cg.v2.u64 {%0,%1}, [%2];"
                 : "=l"(x0), "=l"(x1) : "l"(p) : "memory");
}

// ---------------------------------------------------------------------------
// Phase 1: retention scan with decay halo (decay=0.9 -> 256-step halo exact
// to ~2e-12 relative).
// ---------------------------------------------------------------------------
__global__ void scan_kernel(const float* __restrict__ q,
                            const float* __restrict__ k,
                            const float* __restrict__ v,
                            const float* __restrict__ dec)
{
    int chunk = blockIdx.x;                 // 16 chunks of 128 steps
    int b     = blockIdx.y;
    int d     = blockIdx.z*256 + threadIdx.x;
    float decay = dec[d >> 6];
    int t0 = chunk*128;
    int start = t0 - 256; if (start < 0) start = 0;
    float r = 0.f;
    const float* kb = k + ((size_t)b*S)*D + d;
    const float* vb = v + ((size_t)b*S)*D + d;
    const float* qb = q + ((size_t)b*S)*D + d;
    for (int tt = start; tt < t0 + 128; ++tt) {
        size_t off = (size_t)tt*D;
        r = decay*r + kb[off]*vb[off];
        if (tt >= t0) g_ret[((size_t)tt*B + b)*D + d] = qb[off]*r;
    }
}

// ---------------------------------------------------------------------------
// fp32 SGEMM: C[m,n] = sum_k X[m,k]*W[n,k] (+bias) (+Cin). M=8192, N=K=1024.
// 128x128 tile, BK=8, 256 thr, 8x8/thread, double-buffered smem, f32x2 FMA.
// ---------------------------------------------------------------------------
__global__ __launch_bounds__(256, 2)
void sgemm_kernel(const float* __restrict__ X, const float* __restrict__ W,
                  const float* __restrict__ bias, const float* Cin,
                  float* Cout, int permute)
{
    __shared__ float As[2][8][128];
    __shared__ float Bs[2][8][128];

    int tid = threadIdx.x;
    int m0 = blockIdx.y*128, n0 = blockIdx.x*128;
    int lrow = tid >> 1;
    int lk4  = (tid & 1)*4;
    const float4* Xg = (const float4*)(X + (size_t)(m0+lrow)*D + lk4);
    const float4* Wg = (const float4*)(W + (size_t)(n0+lrow)*D + lk4);
    int ty = tid >> 4, tx = tid & 15;

    ull acc[8][4];   // 8 rows x 4 col-pairs (f32x2 over adjacent n)
    #pragma unroll
    for (int i = 0; i < 8; ++i)
        #pragma unroll
        for (int j = 0; j < 4; ++j) acc[i][j] = 0ull;

    // prologue: fill buffer 0
    float4 ra = Xg[0], rb = Wg[0];
    As[0][lk4+0][lrow] = ra.x; As[0][lk4+1][lrow] = ra.y;
    As[0][lk4+2][lrow] = ra.z; As[0][lk4+3][lrow] = ra.w;
    Bs[0][lk4+0][lrow] = rb.x; Bs[0][lk4+1][lrow] = rb.y;
    Bs[0][lk4+2][lrow] = rb.z; Bs[0][lk4+3][lrow] = rb.w;
    __syncthreads();

    int cur = 0;
    #pragma unroll 1
    for (int kt = 0; kt < 128; ++kt) {
        float4 ra2, rb2;
        if (kt < 127) { ra2 = Xg[(kt+1)*2]; rb2 = Wg[(kt+1)*2]; }

        #pragma unroll
        for (int kk = 0; kk < 8; ++kk) {
            float4 a0 = *(const float4*)&As[cur][kk][ty*8];
            float4 a1 = *(const float4*)&As[cur][kk][ty*8+4];
            ulonglong2 b0 = *(const ulonglong2*)&Bs[cur][kk][tx*8];
            ulonglong2 b1 = *(const ulonglong2*)&Bs[cur][kk][tx*8+4];
            ull bp[4] = { b0.x, b0.y, b1.x, b1.y };
            ull ad[8];
            ad[0] = pack2(a0.x, a0.x); ad[1] = pack2(a0.y, a0.y);
            ad[2] = pack2(a0.z, a0.z); ad[3] = pack2(a0.w, a0.w);
            ad[4] = pack2(a1.x, a1.x); ad[5] = pack2(a1.y, a1.y);
            ad[6] = pack2(a1.z, a1.z); ad[7] = pack2(a1.w, a1.w);
            #pragma unroll
            for (int i = 0; i < 8; ++i)
                #pragma unroll
                for (int j = 0; j < 4; ++j)
                    fma2(acc[i][j], bp[j], ad[i]);
        }

        if (kt < 127) {
            int nb = cur ^ 1;
            As[nb][lk4+0][lrow] = ra2.x; As[nb][lk4+1][lrow] = ra2.y;
            As[nb][lk4+2][lrow] = ra2.z; As[nb][lk4+3][lrow] = ra2.w;
            Bs[nb][lk4+0][lrow] = rb2.x; Bs[nb][lk4+1][lrow] = rb2.y;
            Bs[nb][lk4+2][lrow] = rb2.z; Bs[nb][lk4+3][lrow] = rb2.w;
            __syncthreads();
            cur = nb;
        }
    }

    #pragma unroll
    for (int i = 0; i < 8; ++i) {
        int m = m0 + ty*8 + i;
        size_t obase;
        if (!permute) obase = (size_t)m*D;
        else { int t = m >> 2; int bb = m & 3; obase = ((size_t)bb*S + t)*D; }
        #pragma unroll
        for (int j = 0; j < 4; ++j) {
            float2 v = unpack2(acc[i][j]);
            int n = n0 + tx*8 + j*2;
            float v0 = v.x, v1 = v.y;
            if (bias) { v0 += bias[n]; v1 += bias[n+1]; }
            if (Cin)  { v0 += Cin[(size_t)m*D + n]; v1 += Cin[(size_t)m*D + n+1]; }
            Cout[obase + n]   = v0;
            Cout[obase + n+1] = v1;
        }
    }
}

// ---------------------------------------------------------------------------
// gate = sigmoid(gpre); u = (1-gate)*inp
// ---------------------------------------------------------------------------
__global__ void gate_kernel()
{
    size_t i = (size_t)blockIdx.x*blockDim.x + threadIdx.x;
    if (i < (size_t)M_ROWS*D) {
        float gp = g_gpre[i];
        float gt = 1.f/(1.f + expf(-gp));
        g_gate[i] = gt;
        g_u[i]    = (1.f - gt)*g_inp[i];
    }
}

// ---------------------------------------------------------------------------
// Sequential phase: state_t = tanh((g_t (*) state_{t-1}) @ A^T + d_t)
// 4 independent batch groups x 32 CTAs x 512 threads.
// Lane owns one output column; warp owns a 64-wide k-slice (A in regs).
// Readers fetch blended via uniform-address ld.global.cg broadcasts.
// Writers (tid<32) produce state AND next blended row directly.
// ---------------------------------------------------------------------------
__global__ __launch_bounds__(512, 1)
void seq_kernel(const float* __restrict__ A)
{
    __shared__ float red[16*32];

    int tid = threadIdx.x;
    int w   = tid >> 5, l = tid & 31;
    int grp = blockIdx.x & 3;          // batch
    int cid = blockIdx.x >> 2;         // 0..31 within group
    int col = cid*32 + l;
    int k0  = w*64;

    // Register-resident A slice: A[col, k0 .. k0+63] as 32 f32x2 pairs
    ull A2[32];
    {
        const ulonglong2* ap = (const ulonglong2*)(A + (size_t)col*D + k0);
        #pragma unroll
        for (int i = 0; i < 16; ++i) {
            ulonglong2 u = ap[i];
            A2[2*i] = u.x; A2[2*i+1] = u.y;
        }
    }

    unsigned int* bar = &g_bars[grp*32];

    // writer-lane prefetch state: d row for step t, gate row for step t+1
    float dval = 0.f, gval = 0.f;
    if (tid < 32) {
        dval = __ldg(&g_c   [((size_t)0*B + grp)*D + col]);
        gval = __ldg(&g_gate[((size_t)1*B + grp)*D + col]);
    }

    for (int t = 0; t < S; ++t) {
        const float* gb = g_blend[t & 1][grp] + k0;

        ull acc[4] = {0ull, 0ull, 0ull, 0ull};
        #pragma unroll
        for (int i = 0; i < 16; ++i) {
            ull x0, x1;
            ld_cg_v2u64(x0, x1, gb + i*4);   // uniform across warp -> broadcast
            fma2(acc[i & 3], x0, A2[2*i]);
            fma2(acc[i & 3], x1, A2[2*i+1]);
        }
        float2 f0 = unpack2(acc[0]), f1 = unpack2(acc[1]);
        float2 f2 = unpack2(acc[2]), f3 = unpack2(acc[3]);
        red[w*32 + l] = (f0.x + f0.y) + (f1.x + f1.y)
                      + (f2.x + f2.y) + (f3.x + f3.y);
        __syncthreads();

        if (tid < 32) {
            float s0 = 0.f, s1 = 0.f, s2 = 0.f, s3 = 0.f;
            #pragma unroll
            for (int ww = 0; ww < 16; ww += 4) {
                s0 += red[(ww+0)*32 + tid];
                s1 += red[(ww+1)*32 + tid];
                s2 += red[(ww+2)*32 + tid];
                s3 += red[(ww+3)*32 + tid];
            }
            float st = tanhf((s0 + s1) + (s2 + s3) + dval);
            g_states[((size_t)t*B + grp)*D + col] = st;
            if (t+1 < S) {
                g_blend[(t+1) & 1][grp][col] = gval * st;
                dval = __ldcg(&g_c[((size_t)(t+1)*B + grp)*D + col]);
                if (t+2 < S)
                    gval = __ldcg(&g_gate[((size_t)(t+2)*B + grp)*D + col]);
            }
        }
        __syncthreads();

        if (t+1 < S) {
            if (tid == 0) {
                __threadfence();
                unsigned int old;
                asm volatile("atom.add.release.gpu.u32 %0, [%1], 1;"
                             : "=r"(old) : "l"(bar) : "memory");
                unsigned int target = (unsigned int)(t + 1)*32u;
                while (ld_acq(bar) < target) { }
            }
            __syncthreads();
        }
    }
}

// ---------------------------------------------------------------------------
// Launch
// ---------------------------------------------------------------------------
extern "C" void kernel_launch(void* const* d_in, const int* in_sizes, int n_in,
                              void* d_out, int out_size)
{
    const float* q   = (const float*)d_in[0];
    const float* k   = (const float*)d_in[1];
    const float* v   = (const float*)d_in[2];
    const float* Wi  = (const float*)d_in[3];
    const float* bi  = (const float*)d_in[4];
    const float* Wg  = (const float*)d_in[5];
    const float* bg  = (const float*)d_in[6];
    const float* A   = (const float*)d_in[7];
    const float* Bm  = (const float*)d_in[8];
    const float* Wo  = (const float*)d_in[9];
    const float* bo  = (const float*)d_in[10];
    const float* dec = (const float*)d_in[11];
    float* out = (float*)d_out;

    float *ret_p, *inp_p, *gpre_p, *c_p, *u_p, *states_p;
    cudaGetSymbolAddress((void**)&ret_p,    g_ret);
    cudaGetSymbolAddress((void**)&inp_p,    g_inp);
    cudaGetSymbolAddress((void**)&gpre_p,   g_gpre);
    cudaGetSymbolAddress((void**)&c_p,      g_c);
    cudaGetSymbolAddress((void**)&u_p,      g_u);
    cudaGetSymbolAddress((void**)&states_p, g_states);

    init_misc_kernel<<<32, 256>>>();

    dim3 sg(16, 4, 4);
    scan_kernel<<<sg, 256>>>(q, k, v, dec);

    dim3 gg(D/128, M_ROWS/128);   // (8, 64)
    sgemm_kernel<<<gg, 256>>>(ret_p, Wi, bi, nullptr, inp_p, 0);
    sgemm_kernel<<<gg, 256>>>(inp_p, Wg, bg, nullptr, gpre_p, 0);
    sgemm_kernel<<<gg, 256>>>(inp_p, Bm, nullptr, nullptr, c_p, 0);
    gate_kernel<<<M_ROWS*(D/256), 256>>>();
    sgemm_kernel<<<gg, 256>>>(u_p, A, nullptr, c_p, c_p, 0);
    seq_kernel<<<128, 512>>>(A);
    sgemm_kernel<<<gg, 256>>>(states_p, Wo, bo, nullptr, out, 1);
}